// round 4
// baseline (speedup 1.0000x reference)
#include <cuda_runtime.h>

#define NN 50000
#define EE 400000
#define HH 128
#define OUTD 64
#define NB 3
#define NITERS 2
#define EPS_ 0.01f

// ---------------- scratch (device globals; no allocation allowed) ----------------
__device__ float g_x[NN * HH];    // current node features
__device__ float g_v[NN * HH];    // velocity
__device__ float g_P[NN * HH];    // x @ Wa^T   (also reused as mlp temp)
__device__ float g_Q[NN * HH];    // x @ Wb^T
__device__ float g_f[NN * HH];    // x @ lap_w^T
__device__ float g_d[NN * HH];    // dissipative = relu(x @ diss_w^T + b)
__device__ float g_g[NN * HH];    // scatter accumulator
__device__ float g_r[EE];         // edge resistance
__device__ float g_deg[NN];       // weighted degree

// ---------------- packed f32x2 FMA (PTX-only pattern; doubles fp32 rate) ----------
__device__ __forceinline__ float2 ffma2f(float2 a, float2 b, float2 c) {
    float2 d;
    asm("fma.rn.f32x2 %0, %1, %2, %3;"
        : "=l"(reinterpret_cast<unsigned long long&>(d))
        : "l"(reinterpret_cast<unsigned long long&>(a)),
          "l"(reinterpret_cast<unsigned long long&>(b)),
          "l"(reinterpret_cast<unsigned long long&>(c)));
    return d;
}

// ---------------- generic K=128 GEMM:  C[M,NOUT] = A[M,128] @ W^T (+bias, act) ----
// W is row-major [NOUT, wld], using columns [koff, koff+128).
// act: 0 = none, 1 = relu, 2 = tanh
template <int NOUT>
__global__ void __launch_bounds__(256)
gemm_k128(const float* __restrict__ A, int M,
          const float* __restrict__ W, int wld, int koff,
          const float* __restrict__ bias, int act,
          float* __restrict__ C, int ldc) {
    constexpr int TM = 64;
    constexpr int RT = 4;            // rows per thread
    constexpr int CT = NOUT / 16;    // cols per thread
    extern __shared__ float sm[];
    float* sA = sm;                  // [TM][130]  (pad 2 -> float2-aligned, conflict-free)
    float* sW = sm + TM * 130;       // [NOUT][130]

    int tid = threadIdx.x;
    int r0 = blockIdx.x * TM;

    for (int i = tid; i < NOUT * 128; i += 256) {
        int c = i >> 7, k = i & 127;
        sW[c * 130 + k] = W[(size_t)c * wld + koff + k];
    }
    for (int i = tid; i < TM * 128; i += 256) {
        int rr = i >> 7, k = i & 127;
        int row = r0 + rr;
        sA[rr * 130 + k] = (row < M) ? A[(size_t)row * 128 + k] : 0.f;
    }
    __syncthreads();

    const float2* sA2 = (const float2*)sA;   // row stride 65 float2
    const float2* sW2 = (const float2*)sW;
    int tx = tid & 15, ty = tid >> 4;

    float2 acc[RT][CT];
#pragma unroll
    for (int i = 0; i < RT; i++)
#pragma unroll
        for (int j = 0; j < CT; j++) acc[i][j] = make_float2(0.f, 0.f);

#pragma unroll 8
    for (int kp = 0; kp < 64; kp++) {
        float2 a[RT], w[CT];
#pragma unroll
        for (int i = 0; i < RT; i++) a[i] = sA2[(ty + i * 16) * 65 + kp];
#pragma unroll
        for (int j = 0; j < CT; j++) w[j] = sW2[(tx + j * 16) * 65 + kp];
#pragma unroll
        for (int i = 0; i < RT; i++)
#pragma unroll
            for (int j = 0; j < CT; j++) acc[i][j] = ffma2f(a[i], w[j], acc[i][j]);
    }

#pragma unroll
    for (int i = 0; i < RT; i++) {
        int row = r0 + ty + i * 16;
        if (row < M) {
#pragma unroll
            for (int j = 0; j < CT; j++) {
                int c = tx + j * 16;
                float val = acc[i][j].x + acc[i][j].y;
                if (bias) val += bias[c];
                if (act == 1) val = fmaxf(val, 0.f);
                else if (act == 2) val = tanhf(val);
                C[(size_t)row * ldc + c] = val;
            }
        }
    }
}

// ---------------- edge resistance: r[e] = |sum_j relu(P[s]+Q[d]+b1)[j]*w2[j] + b2|
// one warp per edge; lane covers 4 channels (float4). Also accumulates deg[src].
__global__ void __launch_bounds__(256)
edge_resist(const int* __restrict__ src, const int* __restrict__ dst,
            const float* __restrict__ b1, const float* __restrict__ w2,
            const float* __restrict__ b2) {
    int e = (blockIdx.x * blockDim.x + threadIdx.x) >> 5;
    int lane = threadIdx.x & 31;
    if (e >= EE) return;
    int s = src[e], d = dst[e];
    float4 p = *(const float4*)(g_P + (size_t)s * HH + lane * 4);
    float4 q = *(const float4*)(g_Q + (size_t)d * HH + lane * 4);
    float4 bb = *(const float4*)(b1 + lane * 4);
    float4 ww = *(const float4*)(w2 + lane * 4);
    float sum = fmaxf(p.x + q.x + bb.x, 0.f) * ww.x
              + fmaxf(p.y + q.y + bb.y, 0.f) * ww.y
              + fmaxf(p.z + q.z + bb.z, 0.f) * ww.z
              + fmaxf(p.w + q.w + bb.w, 0.f) * ww.w;
#pragma unroll
    for (int off = 16; off > 0; off >>= 1) sum += __shfl_xor_sync(0xFFFFFFFFu, sum, off);
    if (lane == 0) {
        float rr = fabsf(sum + b2[0]);
        g_r[e] = rr;
        atomicAdd(&g_deg[s], rr);
    }
}

// ---------------- scatter: g[dst] += r[e] * f[src]  (vec4 reductions) ----------
__global__ void __launch_bounds__(256)
scatter_edges(const int* __restrict__ src, const int* __restrict__ dst) {
    int e = (blockIdx.x * blockDim.x + threadIdx.x) >> 5;
    int lane = threadIdx.x & 31;
    if (e >= EE) return;
    float rr = g_r[e];
    int s = src[e], d = dst[e];
    float4 fv = *(const float4*)(g_f + (size_t)s * HH + lane * 4);
    float* gp = g_g + (size_t)d * HH + lane * 4;
    asm volatile("red.global.add.v4.f32 [%0], {%1,%2,%3,%4};"
                 :: "l"(gp), "f"(rr * fv.x), "f"(rr * fv.y), "f"(rr * fv.z), "f"(rr * fv.w)
                 : "memory");
}

// ---------------- node update: v -= eps*((deg*f - g) + diss*v); x += eps*v ------
__global__ void __launch_bounds__(256)
update_nodes() {
    int i4 = blockIdx.x * blockDim.x + threadIdx.x;
    if (i4 >= NN * HH / 4) return;
    int row = i4 >> 5;  // 128/4 = 32 float4 per row
    float dg = g_deg[row];
    float4 f4 = ((const float4*)g_f)[i4];
    float4 gg = ((const float4*)g_g)[i4];
    float4 ds = ((const float4*)g_d)[i4];
    float4 vv = ((const float4*)g_v)[i4];
    float4 xx = ((const float4*)g_x)[i4];
    vv.x -= EPS_ * ((dg * f4.x - gg.x) + ds.x * vv.x);
    vv.y -= EPS_ * ((dg * f4.y - gg.y) + ds.y * vv.y);
    vv.z -= EPS_ * ((dg * f4.z - gg.z) + ds.z * vv.z);
    vv.w -= EPS_ * ((dg * f4.w - gg.w) + ds.w * vv.w);
    xx.x += EPS_ * vv.x;
    xx.y += EPS_ * vv.y;
    xx.z += EPS_ * vv.z;
    xx.w += EPS_ * vv.w;
    ((float4*)g_v)[i4] = vv;
    ((float4*)g_x)[i4] = xx;
}

// ------------------------------- driver ---------------------------------------
extern "C" void kernel_launch(void* const* d_in, const int* in_sizes, int n_in,
                              void* d_out, int out_size) {
    const float* x_in   = (const float*)d_in[0];
    const int*   ei     = (const int*)  d_in[1];
    const float* emb_w  = (const float*)d_in[2];
    const float* emb_b  = (const float*)d_in[3];
    const float* lap_w  = (const float*)d_in[4];
    const float* er_w1  = (const float*)d_in[5];
    const float* er_b1  = (const float*)d_in[6];
    const float* er_w2  = (const float*)d_in[7];
    const float* er_b2  = (const float*)d_in[8];
    const float* diss_w = (const float*)d_in[9];
    const float* diss_b = (const float*)d_in[10];
    const float* mlp_w1 = (const float*)d_in[11];
    const float* mlp_b1 = (const float*)d_in[12];
    const float* mlp_w2 = (const float*)d_in[13];
    const float* mlp_b2 = (const float*)d_in[14];
    const float* ro_w   = (const float*)d_in[15];
    const float* ro_b   = (const float*)d_in[16];
    const int* src = ei;
    const int* dst = ei + EE;

    float *px, *pv, *pP, *pQ, *pf, *pd, *pg, *pdeg;
    cudaGetSymbolAddress((void**)&px, g_x);
    cudaGetSymbolAddress((void**)&pv, g_v);
    cudaGetSymbolAddress((void**)&pP, g_P);
    cudaGetSymbolAddress((void**)&pQ, g_Q);
    cudaGetSymbolAddress((void**)&pf, g_f);
    cudaGetSymbolAddress((void**)&pd, g_d);
    cudaGetSymbolAddress((void**)&pg, g_g);
    cudaGetSymbolAddress((void**)&pdeg, g_deg);

    const int SM128 = (64 + 128) * 130 * 4;  // 99840
    const int SM64  = (64 + 64) * 130 * 4;   // 66560
    cudaFuncSetAttribute(gemm_k128<128>, cudaFuncAttributeMaxDynamicSharedMemorySize, SM128);
    cudaFuncSetAttribute(gemm_k128<64>,  cudaFuncAttributeMaxDynamicSharedMemorySize, SM64);

    const int GB = (NN + 63) / 64;       // 782 CTAs
    const int EB = EE / 8;               // 50000 CTAs (8 warps/CTA, 1 warp/edge)
    const int UB = (NN * HH / 4 + 255) / 256;

    // x = x_in @ emb_w^T + emb_b
    gemm_k128<128><<<GB, 256, SM128>>>(x_in, NN, emb_w, 128, 0, emb_b, 0, px, 128);

    for (int b = 0; b < NB; b++) {
        const float* w1 = er_w1 + (size_t)b * HH * 2 * HH;
        // P = x @ Wa^T, Q = x @ Wb^T   (concat split of the edge-resistance GEMM)
        gemm_k128<128><<<GB, 256, SM128>>>(px, NN, w1, 256, 0,   nullptr, 0, pP, 128);
        gemm_k128<128><<<GB, 256, SM128>>>(px, NN, w1, 256, 128, nullptr, 0, pQ, 128);
        cudaMemsetAsync(pdeg, 0, NN * sizeof(float), 0);
        cudaMemsetAsync(pv, 0, (size_t)NN * HH * sizeof(float), 0);
        edge_resist<<<EB, 256>>>(src, dst, er_b1 + (size_t)b * HH,
                                 er_w2 + (size_t)b * HH, er_b2 + b);
        for (int it = 0; it < NITERS; it++) {
            gemm_k128<128><<<GB, 256, SM128>>>(px, NN, lap_w + (size_t)b * HH * HH, 128, 0,
                                               nullptr, 0, pf, 128);
            gemm_k128<128><<<GB, 256, SM128>>>(px, NN, diss_w + (size_t)b * HH * HH, 128, 0,
                                               diss_b + (size_t)b * HH, 1, pd, 128);
            cudaMemsetAsync(pg, 0, (size_t)NN * HH * sizeof(float), 0);
            scatter_edges<<<EB, 256>>>(src, dst);
            update_nodes<<<UB, 256>>>();
        }
        // x = tanh(x @ mlp_w1^T + b1) @ mlp_w2^T + b2   (reuse g_P as temp)
        gemm_k128<128><<<GB, 256, SM128>>>(px, NN, mlp_w1 + (size_t)b * HH * HH, 128, 0,
                                           mlp_b1 + (size_t)b * HH, 2, pP, 128);
        gemm_k128<128><<<GB, 256, SM128>>>(pP, NN, mlp_w2 + (size_t)b * HH * HH, 128, 0,
                                           mlp_b2 + (size_t)b * HH, 0, px, 128);
    }

    // out = x @ ro_w^T + ro_b
    gemm_k128<64><<<GB, 256, SM64>>>(px, NN, ro_w, 128, 0, ro_b, 0, (float*)d_out, 64);
}

// round 8
// speedup vs baseline: 1.1965x; 1.1965x over previous
#include <cuda_runtime.h>
#include <cuda_bf16.h>
#include <cstdint>

#define NN 50000
#define EE 400000
#define HH 128
#define NB 3
#define NITERS 2
#define EPS_ 0.01f

// ---------------- scratch (device globals; no allocation allowed) ----------------
__device__ float g_x[NN * HH];
__device__ float g_v[NN * HH];
__device__ float g_P[NN * HH];
__device__ float g_Q[NN * HH];
__device__ float g_f[NN * HH];
__device__ float g_d[NN * HH];
__device__ float g_g[NN * HH];
__device__ float g_r[EE];
__device__ float g_deg[NN];
// pre-split weights, plain row-major [slot][n][k] bf16 (slot19 = readout, 64x128)
__device__ __nv_bfloat16 g_Wh[20 * 128 * 128];
__device__ __nv_bfloat16 g_Wl[20 * 128 * 128];

__device__ __forceinline__ uint32_t smem_u32(const void* p) {
    uint32_t a;
    asm("{ .reg .u64 t; cvta.to.shared.u64 t, %1; cvt.u32.u64 %0, t; }" : "=r"(a) : "l"(p));
    return a;
}

// ---------------- weight pre-split (runs once per launch) -----------------------
__global__ void convert_weights(const float* __restrict__ emb_w, const float* __restrict__ er_w1,
                                const float* __restrict__ lap_w, const float* __restrict__ diss_w,
                                const float* __restrict__ mlp_w1, const float* __restrict__ mlp_w2,
                                const float* __restrict__ ro_w) {
    int slot = blockIdx.y;
    int rows = (slot == 19) ? 64 : 128;
    int idx = blockIdx.x * 256 + threadIdx.x;
    if (idx >= rows * 128) return;
    int r = idx >> 7, k = idx & 127;
    const float* srcp;
    int wld = 128, koff = 0;
    if (slot == 0) srcp = emb_w;
    else if (slot == 19) srcp = ro_w;
    else {
        int b = (slot - 1) / 6, j = (slot - 1) % 6;
        if (j == 0)      { srcp = er_w1 + (size_t)b * 128 * 256; wld = 256; }
        else if (j == 1) { srcp = er_w1 + (size_t)b * 128 * 256; wld = 256; koff = 128; }
        else if (j == 2) srcp = lap_w  + (size_t)b * 16384;
        else if (j == 3) srcp = diss_w + (size_t)b * 16384;
        else if (j == 4) srcp = mlp_w1 + (size_t)b * 16384;
        else             srcp = mlp_w2 + (size_t)b * 16384;
    }
    float x = srcp[(size_t)r * wld + koff + k];
    __nv_bfloat16 hi = __float2bfloat16(x);
    __nv_bfloat16 lo = __float2bfloat16(x - __bfloat162float(hi));
    g_Wh[slot * 16384 + idx] = hi;
    g_Wl[slot * 16384 + idx] = lo;
}

// ---------------- mma.sync bf16 GEMM: C[M,NOUT] = A[M,128] @ W^T (+bias, act) ---
// double-bf16 split: C = Ah*Bh + Ah*Bl + Al*Bh   (fp32 accumulators)
// act: 0 none, 1 relu, 2 tanh
#define SPAD 136   // smem row stride in bf16 elems (272 B -> conflict-free LDSM)
template <int NOUT>
__global__ void __launch_bounds__(256)
gemm_tc(const float* __restrict__ A, int M,
        const __nv_bfloat16* __restrict__ Bh, const __nv_bfloat16* __restrict__ Bl,
        const float* __restrict__ bias, int act, float* __restrict__ C) {
    constexpr int NT = NOUT / 8;      // n8-tiles per warp row-band
    extern __shared__ char sm[];
    float* sbias = (float*)sm;                               // [NOUT]
    __nv_bfloat16* sAh = (__nv_bfloat16*)(sm + 1024);        // [128][SPAD]
    __nv_bfloat16* sAl = sAh + 128 * SPAD;
    __nv_bfloat16* sBh = sAl + 128 * SPAD;                   // [NOUT][SPAD]
    __nv_bfloat16* sBl = sBh + NOUT * SPAD;

    int tid = threadIdx.x, wid = tid >> 5, lane = tid & 31;
    int r0 = blockIdx.x * 128;

    // B: copy pre-split weights (row-major) into padded smem
    for (int i = tid; i < NOUT * 64; i += 256) {
        int n = i >> 6, kp = (i & 63);
        ((uint32_t*)(sBh + n * SPAD))[kp] = ((const uint32_t*)(Bh + n * 128))[kp];
        ((uint32_t*)(sBl + n * SPAD))[kp] = ((const uint32_t*)(Bl + n * 128))[kp];
    }
    if (tid < NOUT) sbias[tid] = bias ? bias[tid] : 0.f;

    // A: load fp32, split hi/lo bf16 into padded smem
    for (int i = tid; i < 128 * 64; i += 256) {
        int row = i >> 6, k = (i & 63) << 1;
        float2 a = make_float2(0.f, 0.f);
        if (r0 + row < M) a = *(const float2*)(A + (size_t)(r0 + row) * 128 + k);
        __nv_bfloat16 h0 = __float2bfloat16(a.x);
        __nv_bfloat16 h1 = __float2bfloat16(a.y);
        __nv_bfloat162 hp; hp.x = h0; hp.y = h1;
        __nv_bfloat162 lp;
        lp.x = __float2bfloat16(a.x - __bfloat162float(h0));
        lp.y = __float2bfloat16(a.y - __bfloat162float(h1));
        *(__nv_bfloat162*)(sAh + row * SPAD + k) = hp;
        *(__nv_bfloat162*)(sAl + row * SPAD + k) = lp;
    }
    __syncthreads();

    float acc[NT][4];
#pragma unroll
    for (int t = 0; t < NT; t++)
#pragma unroll
        for (int j = 0; j < 4; j++) acc[t][j] = 0.f;

    // ldmatrix base addresses (lane-dependent row/col mapping)
    // A (.x4, m16k16): row = wid*16 + lane%16, kcol = (lane/16)*8
    uint32_t aRow = wid * 16 + (lane & 15), aCol = (lane >> 4) << 3;
    // B (.x4, two n8-tiles x k16): n = (lane>>4)*8 + (lane&7), kcol = ((lane>>3)&1)*8
    uint32_t bRow = ((lane >> 4) << 3) + (lane & 7), bCol = ((lane >> 3) & 1) << 3;

#pragma unroll
    for (int term = 0; term < 3; term++) {
        const __nv_bfloat16* pA = (term == 2) ? sAl : sAh;
        const __nv_bfloat16* pB = (term == 1) ? sBl : sBh;
        uint32_t aBase = smem_u32(pA) + (aRow * SPAD + aCol) * 2;
        uint32_t bBase = smem_u32(pB) + (bRow * SPAD + bCol) * 2;
#pragma unroll
        for (int kk = 0; kk < 8; kk++) {
            uint32_t a0, a1, a2, a3;
            asm volatile("ldmatrix.sync.aligned.m8n8.x4.shared.b16 {%0,%1,%2,%3}, [%4];"
                         : "=r"(a0), "=r"(a1), "=r"(a2), "=r"(a3)
                         : "r"(aBase + kk * 32));
#pragma unroll
            for (int np = 0; np < NT / 2; np++) {
                uint32_t b0, b1, b2, b3;
                asm volatile("ldmatrix.sync.aligned.m8n8.x4.shared.b16 {%0,%1,%2,%3}, [%4];"
                             : "=r"(b0), "=r"(b1), "=r"(b2), "=r"(b3)
                             : "r"(bBase + (np * 16 * SPAD) * 2 + kk * 32));
                asm volatile(
                    "mma.sync.aligned.m16n8k16.row.col.f32.bf16.bf16.f32 "
                    "{%0,%1,%2,%3}, {%4,%5,%6,%7}, {%8,%9}, {%0,%1,%2,%3};"
                    : "+f"(acc[np * 2][0]), "+f"(acc[np * 2][1]),
                      "+f"(acc[np * 2][2]), "+f"(acc[np * 2][3])
                    : "r"(a0), "r"(a1), "r"(a2), "r"(a3), "r"(b0), "r"(b1));
                asm volatile(
                    "mma.sync.aligned.m16n8k16.row.col.f32.bf16.bf16.f32 "
                    "{%0,%1,%2,%3}, {%4,%5,%6,%7}, {%8,%9}, {%0,%1,%2,%3};"
                    : "+f"(acc[np * 2 + 1][0]), "+f"(acc[np * 2 + 1][1]),
                      "+f"(acc[np * 2 + 1][2]), "+f"(acc[np * 2 + 1][3])
                    : "r"(a0), "r"(a1), "r"(a2), "r"(a3), "r"(b2), "r"(b3));
            }
        }
    }

    // epilogue: c fragment (r=lane/4 [+8], n=2*(lane%4)+{0,1}) per n-tile
    int rA = r0 + wid * 16 + (lane >> 2);
    int cB = 2 * (lane & 3);
#pragma unroll
    for (int t = 0; t < NT; t++) {
        int col = t * 8 + cB;
        float2 u0 = make_float2(acc[t][0] + sbias[col], acc[t][1] + sbias[col + 1]);
        float2 u1 = make_float2(acc[t][2] + sbias[col], acc[t][3] + sbias[col + 1]);
        if (act == 1) {
            u0.x = fmaxf(u0.x, 0.f); u0.y = fmaxf(u0.y, 0.f);
            u1.x = fmaxf(u1.x, 0.f); u1.y = fmaxf(u1.y, 0.f);
        } else if (act == 2) {
            u0.x = tanhf(u0.x); u0.y = tanhf(u0.y);
            u1.x = tanhf(u1.x); u1.y = tanhf(u1.y);
        }
        if (rA < M)     *(float2*)(C + (size_t)rA * NOUT + col) = u0;
        if (rA + 8 < M) *(float2*)(C + (size_t)(rA + 8) * NOUT + col) = u1;
    }
}

// ---------------- edge resistance (unchanged) -----------------------------------
__global__ void __launch_bounds__(256)
edge_resist(const int* __restrict__ src, const int* __restrict__ dst,
            const float* __restrict__ b1, const float* __restrict__ w2,
            const float* __restrict__ b2) {
    int e = (blockIdx.x * blockDim.x + threadIdx.x) >> 5;
    int lane = threadIdx.x & 31;
    if (e >= EE) return;
    int s = src[e], d = dst[e];
    float4 p = *(const float4*)(g_P + (size_t)s * HH + lane * 4);
    float4 q = *(const float4*)(g_Q + (size_t)d * HH + lane * 4);
    float4 bb = *(const float4*)(b1 + lane * 4);
    float4 ww = *(const float4*)(w2 + lane * 4);
    float sum = fmaxf(p.x + q.x + bb.x, 0.f) * ww.x
              + fmaxf(p.y + q.y + bb.y, 0.f) * ww.y
              + fmaxf(p.z + q.z + bb.z, 0.f) * ww.z
              + fmaxf(p.w + q.w + bb.w, 0.f) * ww.w;
#pragma unroll
    for (int off = 16; off > 0; off >>= 1) sum += __shfl_xor_sync(0xFFFFFFFFu, sum, off);
    if (lane == 0) {
        float rr = fabsf(sum + b2[0]);
        g_r[e] = rr;
        atomicAdd(&g_deg[s], rr);
    }
}

// ---------------- scatter (unchanged) -------------------------------------------
__global__ void __launch_bounds__(256)
scatter_edges(const int* __restrict__ src, const int* __restrict__ dst) {
    int e = (blockIdx.x * blockDim.x + threadIdx.x) >> 5;
    int lane = threadIdx.x & 31;
    if (e >= EE) return;
    float rr = g_r[e];
    int s = src[e], d = dst[e];
    float4 fv = *(const float4*)(g_f + (size_t)s * HH + lane * 4);
    float* gp = g_g + (size_t)d * HH + lane * 4;
    asm volatile("red.global.add.v4.f32 [%0], {%1,%2,%3,%4};"
                 :: "l"(gp), "f"(rr * fv.x), "f"(rr * fv.y), "f"(rr * fv.z), "f"(rr * fv.w)
                 : "memory");
}

// ---------------- node update (unchanged) ---------------------------------------
__global__ void __launch_bounds__(256)
update_nodes() {
    int i4 = blockIdx.x * blockDim.x + threadIdx.x;
    if (i4 >= NN * HH / 4) return;
    int row = i4 >> 5;
    float dg = g_deg[row];
    float4 f4 = ((const float4*)g_f)[i4];
    float4 gg = ((const float4*)g_g)[i4];
    float4 ds = ((const float4*)g_d)[i4];
    float4 vv = ((const float4*)g_v)[i4];
    float4 xx = ((const float4*)g_x)[i4];
    vv.x -= EPS_ * ((dg * f4.x - gg.x) + ds.x * vv.x);
    vv.y -= EPS_ * ((dg * f4.y - gg.y) + ds.y * vv.y);
    vv.z -= EPS_ * ((dg * f4.z - gg.z) + ds.z * vv.z);
    vv.w -= EPS_ * ((dg * f4.w - gg.w) + ds.w * vv.w);
    xx.x += EPS_ * vv.x;
    xx.y += EPS_ * vv.y;
    xx.z += EPS_ * vv.z;
    xx.w += EPS_ * vv.w;
    ((float4*)g_v)[i4] = vv;
    ((float4*)g_x)[i4] = xx;
}

// ------------------------------- driver -----------------------------------------
extern "C" void kernel_launch(void* const* d_in, const int* in_sizes, int n_in,
                              void* d_out, int out_size) {
    const float* x_in   = (const float*)d_in[0];
    const int*   ei     = (const int*)  d_in[1];
    const float* emb_w  = (const float*)d_in[2];
    const float* emb_b  = (const float*)d_in[3];
    const float* lap_w  = (const float*)d_in[4];
    const float* er_w1  = (const float*)d_in[5];
    const float* er_b1  = (const float*)d_in[6];
    const float* er_w2  = (const float*)d_in[7];
    const float* er_b2  = (const float*)d_in[8];
    const float* diss_w = (const float*)d_in[9];
    const float* diss_b = (const float*)d_in[10];
    const float* mlp_w1 = (const float*)d_in[11];
    const float* mlp_b1 = (const float*)d_in[12];
    const float* mlp_w2 = (const float*)d_in[13];
    const float* mlp_b2 = (const float*)d_in[14];
    const float* ro_w   = (const float*)d_in[15];
    const float* ro_b   = (const float*)d_in[16];
    const int* src = ei;
    const int* dst = ei + EE;

    float *px, *pv, *pP, *pQ, *pf, *pd, *pg, *pdeg;
    cudaGetSymbolAddress((void**)&px, g_x);
    cudaGetSymbolAddress((void**)&pv, g_v);
    cudaGetSymbolAddress((void**)&pP, g_P);
    cudaGetSymbolAddress((void**)&pQ, g_Q);
    cudaGetSymbolAddress((void**)&pf, g_f);
    cudaGetSymbolAddress((void**)&pd, g_d);
    cudaGetSymbolAddress((void**)&pg, g_g);
    cudaGetSymbolAddress((void**)&pdeg, g_deg);
    __nv_bfloat16 *pWh, *pWl;
    cudaGetSymbolAddress((void**)&pWh, g_Wh);
    cudaGetSymbolAddress((void**)&pWl, g_Wl);

    // smem: 1024 (bias) + 2*128*SPAD*2 (A) + 2*NOUT*SPAD*2 (B)
    const int SMT128 = 1024 + 2 * 128 * SPAD * 2 + 2 * 128 * SPAD * 2;  // 140288
    const int SMT64  = 1024 + 2 * 128 * SPAD * 2 + 2 * 64 * SPAD * 2;   // 105472
    cudaFuncSetAttribute(gemm_tc<128>, cudaFuncAttributeMaxDynamicSharedMemorySize, SMT128);
    cudaFuncSetAttribute(gemm_tc<64>,  cudaFuncAttributeMaxDynamicSharedMemorySize, SMT64);

    const int GT = (NN + 127) / 128;   // 391
    const int EB = EE / 8;
    const int UB = (NN * HH / 4 + 255) / 256;
#define WSLOT(s) (pWh + (s) * 16384), (pWl + (s) * 16384)

    convert_weights<<<dim3(64, 20), 256>>>(emb_w, er_w1, lap_w, diss_w, mlp_w1, mlp_w2, ro_w);

    // x = x_in @ emb_w^T + emb_b
    gemm_tc<128><<<GT, 256, SMT128>>>(x_in, NN, WSLOT(0), emb_b, 0, px);

    for (int b = 0; b < NB; b++) {
        int s0 = 1 + b * 6;
        gemm_tc<128><<<GT, 256, SMT128>>>(px, NN, WSLOT(s0 + 0), nullptr, 0, pP);
        gemm_tc<128><<<GT, 256, SMT128>>>(px, NN, WSLOT(s0 + 1), nullptr, 0, pQ);
        cudaMemsetAsync(pdeg, 0, NN * sizeof(float), 0);
        cudaMemsetAsync(pv, 0, (size_t)NN * HH * sizeof(float), 0);
        edge_resist<<<EB, 256>>>(src, dst, er_b1 + (size_t)b * HH,
                                 er_w2 + (size_t)b * HH, er_b2 + b);
        for (int it = 0; it < NITERS; it++) {
            gemm_tc<128><<<GT, 256, SMT128>>>(px, NN, WSLOT(s0 + 2), nullptr, 0, pf);
            gemm_tc<128><<<GT, 256, SMT128>>>(px, NN, WSLOT(s0 + 3),
                                              diss_b + (size_t)b * HH, 1, pd);
            cudaMemsetAsync(pg, 0, (size_t)NN * HH * sizeof(float), 0);
            scatter_edges<<<EB, 256>>>(src, dst);
            update_nodes<<<UB, 256>>>();
        }
        gemm_tc<128><<<GT, 256, SMT128>>>(px, NN, WSLOT(s0 + 4),
                                          mlp_b1 + (size_t)b * HH, 2, pP);
        gemm_tc<128><<<GT, 256, SMT128>>>(pP, NN, WSLOT(s0 + 5),
                                          mlp_b2 + (size_t)b * HH, 0, px);
    }

    gemm_tc<64><<<GT, 256, SMT64>>>(px, NN, WSLOT(19), ro_b, 0, (float*)d_out);
}